// round 2
// baseline (speedup 1.0000x reference)
#include <cuda_runtime.h>
#include <math.h>

#define NTHREADS 256
#define TILE 64
#define XSTRIDE 68   // TILE + 4 pad (float4-aligned rows, staggered banks)
#define WSTRIDE 132  // 128 + 4 pad (conflict-free weight reads)

#define A_ROWS 181
#define B_OFF   (A_ROWS * XSTRIDE)            // 12308
#define W_OFF   (B_OFF + 128 * XSTRIDE)       // 21012
#define SCREW_OFF (W_OFF + 181 * WSTRIDE)     // 44904
#define SMEM_FLOATS (SCREW_OFF + 6 * TILE)    // 45288
#define SMEM_BYTES  (SMEM_FLOATS * 4)         // 181152 bytes

// One dense layer: Xin [FAN_IN][XSTRIDE] (transposed activations) -> Xout [128][XSTRIDE], ReLU.
// Weights W [128][FAN_IN] row-major in gmem, staged transposed into Wt [FAN_IN][WSTRIDE].
// Thread t: ch = t & 127 (output channel), grp = t >> 7 (which 32-point half).
template<int FAN_IN>
__device__ __forceinline__ void dense_layer(
    const float* __restrict__ Wg, const float* __restrict__ bg,
    const float* __restrict__ Xin, float* __restrict__ Xout,
    float* __restrict__ Wt, int ch, int grp)
{
    __syncthreads();  // previous layer done reading Wt / writing Xin
    #pragma unroll 1
    for (int idx = threadIdx.x; idx < FAN_IN * 128; idx += NTHREADS) {
        int c = idx / FAN_IN;          // FAN_IN is constexpr -> mul/shift
        int k = idx - c * FAN_IN;
        Wt[k * WSTRIDE + c] = __ldg(Wg + idx);   // coalesced read, 4-way-conflict write (cheap)
    }
    __syncthreads();

    float bias = __ldg(bg + ch);
    const float* xin = Xin + grp * 32;
    float* xout = Xout + ch * XSTRIDE + grp * 32;

    #pragma unroll 1
    for (int pg = 0; pg < 4; ++pg) {
        float a0 = bias, a1 = bias, a2 = bias, a3 = bias;
        float a4 = bias, a5 = bias, a6 = bias, a7 = bias;
        const float* xp = xin + pg * 8;
        const float* wp = Wt + ch;
        #pragma unroll 4
        for (int k = 0; k < FAN_IN; ++k) {
            float w = wp[k * WSTRIDE];                                        // conflict-free LDS
            float4 xa = *reinterpret_cast<const float4*>(xp + k * XSTRIDE);   // broadcast LDS.128
            float4 xb = *reinterpret_cast<const float4*>(xp + k * XSTRIDE + 4);
            a0 = fmaf(w, xa.x, a0);
            a1 = fmaf(w, xa.y, a1);
            a2 = fmaf(w, xa.z, a2);
            a3 = fmaf(w, xa.w, a3);
            a4 = fmaf(w, xb.x, a4);
            a5 = fmaf(w, xb.y, a5);
            a6 = fmaf(w, xb.z, a6);
            a7 = fmaf(w, xb.w, a7);
        }
        float4 o0 = make_float4(fmaxf(a0, 0.f), fmaxf(a1, 0.f), fmaxf(a2, 0.f), fmaxf(a3, 0.f));
        float4 o1 = make_float4(fmaxf(a4, 0.f), fmaxf(a5, 0.f), fmaxf(a6, 0.f), fmaxf(a7, 0.f));
        *reinterpret_cast<float4*>(xout + pg * 8) = o0;
        *reinterpret_cast<float4*>(xout + pg * 8 + 4) = o1;
    }
}

extern "C" __global__ void __launch_bounds__(NTHREADS, 1)
se3_warp_kernel(
    const float* __restrict__ positions,
    const float* __restrict__ directions,
    const float* __restrict__ warp_code,
    const float* __restrict__ W0, const float* __restrict__ b0,
    const float* __restrict__ W1, const float* __restrict__ b1,
    const float* __restrict__ W2, const float* __restrict__ b2,
    const float* __restrict__ W3, const float* __restrict__ b3,
    const float* __restrict__ W4, const float* __restrict__ b4,
    const float* __restrict__ W5, const float* __restrict__ b5,
    const float* __restrict__ Wr, const float* __restrict__ br,
    const float* __restrict__ Wv, const float* __restrict__ bv,
    float* __restrict__ out, int N)
{
    extern __shared__ float sm[];
    float* A     = sm;                 // rows 0..52: 53-dim input (kept for skip), 53..180: activations
    float* B     = sm + B_OFF;         // 128 rows
    float* Wt    = sm + W_OFF;         // staged transposed weights
    float* screw = sm + SCREW_OFF;     // [6][TILE]

    const int tid  = threadIdx.x;
    const int ch   = tid & 127;
    const int grp  = tid >> 7;
    const int base = blockIdx.x * TILE;

    // ---- positional encoding + input assembly: A[feat][p], feat in [0,53) ----
    const float TWO_PI  = 6.283185307179586f;
    const float HALF_PI = 1.5707963267948966f;   // matches jnp's 0.5*pi in f32
    #pragma unroll 1
    for (int idx = tid; idx < 53 * TILE; idx += NTHREADS) {
        int feat = idx >> 6;
        int p = idx & 63;
        int g = base + p; if (g >= N) g = N - 1;
        float val;
        if (feat < 42) {
            int f = (feat < 21) ? feat : feat - 21;
            int i = f / 7;
            int j = f - i * 7;
            float s = (TWO_PI * positions[g * 3 + i]) * (float)(1 << j);
            val = (feat < 21) ? sinf(s) : sinf(s + HALF_PI);
        } else if (feat < 45) {
            val = positions[g * 3 + (feat - 42)];
        } else {
            val = warp_code[g * 8 + (feat - 45)];
        }
        A[feat * XSTRIDE + p] = val;
    }

    // ---- MLP stem: 53 -> 128 -> 128 -> 128 -> [skip concat 181] -> 128 -> 128 ----
    dense_layer<53 >(W0, b0, A,                B,                Wt, ch, grp);
    dense_layer<128>(W1, b1, B,                A + 53 * XSTRIDE, Wt, ch, grp);
    dense_layer<128>(W2, b2, A + 53 * XSTRIDE, B,                Wt, ch, grp);
    dense_layer<128>(W3, b3, B,                A + 53 * XSTRIDE, Wt, ch, grp);
    dense_layer<181>(W4, b4, A,                B,                Wt, ch, grp);  // concat([inp53, x128])
    dense_layer<128>(W5, b5, B,                A + 53 * XSTRIDE, Wt, ch, grp);

    __syncthreads();

    // ---- heads: screw = [v(Wv,bv), r(Wr,br)], 6 x TILE dot-products of length 128 ----
    const float* featp = A + 53 * XSTRIDE;
    #pragma unroll 1
    for (int idx = tid; idx < 6 * TILE; idx += NTHREADS) {
        int o = idx >> 6;
        int p = idx & 63;
        const float* w = (o < 3) ? (Wv + o * 128) : (Wr + (o - 3) * 128);
        float acc = (o < 3) ? __ldg(bv + o) : __ldg(br + (o - 3));
        #pragma unroll 4
        for (int k = 0; k < 128; ++k)
            acc = fmaf(__ldg(w + k), featp[k * XSTRIDE + p], acc);
        screw[idx] = acc;
    }
    __syncthreads();

    // ---- SE(3) exp-map epilogue (replicates reference exactly) ----
    if (tid < TILE) {
        int p = tid;
        int g = base + p;
        if (g < N) {
            float vx = screw[p],        vy = screw[64 + p],  vz = screw[128 + p];
            float wx = screw[192 + p],  wy = screw[256 + p], wz = screw[320 + p];

            float ang2 = fmaxf(wx * wx + wy * wy + wz * wz, 1e-4f);  // jnp.clip(.., eps)
            float ang  = sqrtf(ang2);
            float sa = sinf(ang), ca = cosf(ang);
            float f1 = sa / ang;
            float f2 = (1.0f - ca) / ang2;
            float f3 = (ang - sa) / (ang * ang2);

            // K per reference _hat_pt3d: rows [0,z,-y], [-z,0,x], [y,-x,0]
            float K[3][3] = {{0.f,  wz, -wy},
                             {-wz, 0.f,  wx},
                             { wy, -wx, 0.f}};
            float KK[3][3];
            #pragma unroll
            for (int i = 0; i < 3; ++i)
                #pragma unroll
                for (int j = 0; j < 3; ++j)
                    KK[i][j] = K[i][0] * K[0][j] + K[i][1] * K[1][j] + K[i][2] * K[2][j];

            float R[3][3], V[3][3];
            #pragma unroll
            for (int i = 0; i < 3; ++i)
                #pragma unroll
                for (int j = 0; j < 3; ++j) {
                    float I = (i == j) ? 1.0f : 0.0f;
                    R[i][j] = I + f1 * K[i][j] + f2 * KK[i][j];
                    V[i][j] = I + f2 * K[i][j] + f3 * KK[i][j];
                }
            float T0 = V[0][0] * vx + V[0][1] * vy + V[0][2] * vz;
            float T1 = V[1][0] * vx + V[1][1] * vy + V[1][2] * vz;
            float T2 = V[2][0] * vx + V[2][1] * vy + V[2][2] * vz;

            float px = positions[g * 3 + 0], py = positions[g * 3 + 1], pz = positions[g * 3 + 2];
            float dx = directions[g * 3 + 0], dy = directions[g * 3 + 1], dz = directions[g * 3 + 2];

            // M[:3,:3] = R^T, M[:3,3] = T  =>  wp = R^T p + T, wd = R^T d
            float wp0 = R[0][0] * px + R[1][0] * py + R[2][0] * pz + T0;
            float wp1 = R[0][1] * px + R[1][1] * py + R[2][1] * pz + T1;
            float wp2 = R[0][2] * px + R[1][2] * py + R[2][2] * pz + T2;
            float wd0 = R[0][0] * dx + R[1][0] * dy + R[2][0] * dz;
            float wd1 = R[0][1] * dx + R[1][1] * dy + R[2][1] * dz;
            float wd2 = R[0][2] * dx + R[1][2] * dy + R[2][2] * dz;

            wp0 = isnan(wp0) ? px : wp0;
            wp1 = isnan(wp1) ? py : wp1;
            wp2 = isnan(wp2) ? pz : wp2;
            wd0 = isnan(wd0) ? dx : wd0;
            wd1 = isnan(wd1) ? dy : wd1;
            wd2 = isnan(wd2) ? dz : wd2;

            out[g * 3 + 0] = wp0;
            out[g * 3 + 1] = wp1;
            out[g * 3 + 2] = wp2;
            long long off = 3LL * N;
            out[off + g * 3 + 0] = wd0;
            out[off + g * 3 + 1] = wd1;
            out[off + g * 3 + 2] = wd2;
        }
    }
}

extern "C" void kernel_launch(void* const* d_in, const int* in_sizes, int n_in,
                              void* d_out, int out_size) {
    const float* positions  = (const float*)d_in[0];
    const float* directions = (const float*)d_in[1];
    const float* warp_code  = (const float*)d_in[2];
    const float* W0 = (const float*)d_in[3];  const float* b0 = (const float*)d_in[4];
    const float* W1 = (const float*)d_in[5];  const float* b1 = (const float*)d_in[6];
    const float* W2 = (const float*)d_in[7];  const float* b2 = (const float*)d_in[8];
    const float* W3 = (const float*)d_in[9];  const float* b3 = (const float*)d_in[10];
    const float* W4 = (const float*)d_in[11]; const float* b4 = (const float*)d_in[12];
    const float* W5 = (const float*)d_in[13]; const float* b5 = (const float*)d_in[14];
    const float* Wr = (const float*)d_in[15]; const float* br = (const float*)d_in[16];
    const float* Wv = (const float*)d_in[17]; const float* bv = (const float*)d_in[18];

    int N = in_sizes[0] / 3;
    int blocks = (N + TILE - 1) / TILE;

    cudaFuncSetAttribute(se3_warp_kernel,
                         cudaFuncAttributeMaxDynamicSharedMemorySize, SMEM_BYTES);

    se3_warp_kernel<<<blocks, NTHREADS, SMEM_BYTES>>>(
        positions, directions, warp_code,
        W0, b0, W1, b1, W2, b2, W3, b3, W4, b4, W5, b5,
        Wr, br, Wv, bv,
        (float*)d_out, N);
}

// round 4
// speedup vs baseline: 17.4454x; 17.4454x over previous
#include <cuda_runtime.h>
#include <cuda_bf16.h>
#include <cstdint>
#include <math.h>

// ============================ config ============================
#define NTHREADS 256
#define TILE_M   128

// weight row stride in bf16 elements: 200 (=400 bytes, 100 words; 100%32=4 -> conflict-free ldmatrix rows)
#define WROW_B   400
#define WROW_W   100
#define SLOT_WORDS (128 * WROW_W)      // 12800 u32 per weight slot

// smem layout (bytes)
#define ENC_OFF    0                   // 128 rows x 144 B (72 bf16, k 0..63 used)
#define ENC_ROW_B  144
#define WB0_OFF    18432               // 128 x 400 B
#define WB1_OFF    69632
#define SBIAS0_OFF 120832              // 128 f32
#define SBIAS1_OFF 121344
#define SCREW_OFF  121856              // 128 x 8 f32
#define SMEM_BYTES 125952

__device__ uint32_t g_wscratch[7 * SLOT_WORDS];   // 7 slots: L0..L5, head
__device__ float    g_biasg[6 * 128];

// ============================ helpers ============================
__device__ __forceinline__ uint32_t smem_to_u32(const void* p) {
    uint32_t a;
    asm("{ .reg .u64 t; cvta.to.shared.u64 t, %1; cvt.u32.u64 %0, t; }" : "=r"(a) : "l"(p));
    return a;
}

__device__ __forceinline__ void ldmx4(uint32_t& r0, uint32_t& r1, uint32_t& r2, uint32_t& r3, uint32_t addr) {
    asm volatile("ldmatrix.sync.aligned.m8n8.x4.shared.b16 {%0,%1,%2,%3}, [%4];"
        : "=r"(r0), "=r"(r1), "=r"(r2), "=r"(r3) : "r"(addr));
}

__device__ __forceinline__ void mma_bf16(float (&c)[4],
    uint32_t a0, uint32_t a1, uint32_t a2, uint32_t a3, uint32_t b0, uint32_t b1) {
    asm volatile("mma.sync.aligned.m16n8k16.row.col.f32.bf16.bf16.f32 "
        "{%0,%1,%2,%3}, {%4,%5,%6,%7}, {%8,%9}, {%0,%1,%2,%3};"
        : "+f"(c[0]), "+f"(c[1]), "+f"(c[2]), "+f"(c[3])
        : "r"(a0), "r"(a1), "r"(a2), "r"(a3), "r"(b0), "r"(b1));
}

__device__ __forceinline__ uint32_t pack_bf2(float lo, float hi) {
    __nv_bfloat162 h = __floats2bfloat162_rn(lo, hi);
    return *reinterpret_cast<uint32_t*>(&h);
}

// weight fetch with layer-specific padding/remap
__device__ __forceinline__ float wfetch(int mode, int n, int k, const float* Wa, const float* Wb) {
    if (mode == 0) return __ldg(Wa + n * 128 + k);                   // fan_in 128
    if (mode == 1) return (k < 53) ? __ldg(Wa + n * 53 + k) : 0.0f;  // L0: 53 -> pad 64
    if (mode == 2) {                                                 // L4: concat(53 pad 64, 128)
        if (k < 53) return __ldg(Wa + n * 181 + k);
        if (k < 64) return 0.0f;
        return __ldg(Wa + n * 181 + (k - 11));
    }
    // mode 3: head rows = [Wv0..2, Wr0..2, 0, 0]
    if (n < 3) return __ldg(Wa + n * 128 + k);
    if (n < 6) return __ldg(Wb + (n - 3) * 128 + k);
    return 0.0f;
}

// ============================ prep kernel ============================
__global__ void prep_weights(
    const float* W0, const float* W1, const float* W2, const float* W3,
    const float* W4, const float* W5, const float* Wv, const float* Wr,
    const float* b0, const float* b1, const float* b2, const float* b3,
    const float* b4, const float* b5)
{
    int slot = blockIdx.y;
    int idx = blockIdx.x * 256 + threadIdx.x;
    uint32_t* dst = g_wscratch + slot * SLOT_WORDS;

    const float *Wa = nullptr, *Wb = nullptr, *bb = nullptr;
    int mode = 0, rows = 128, halfK = 64;
    switch (slot) {
        case 0: Wa = W0; mode = 1; halfK = 32; bb = b0; break;
        case 1: Wa = W1; mode = 0; halfK = 64; bb = b1; break;
        case 2: Wa = W2; mode = 0; halfK = 64; bb = b2; break;
        case 3: Wa = W3; mode = 0; halfK = 64; bb = b3; break;
        case 4: Wa = W4; mode = 2; halfK = 96; bb = b4; break;
        case 5: Wa = W5; mode = 0; halfK = 64; bb = b5; break;
        case 6: Wa = Wv; Wb = Wr; mode = 3; rows = 8; halfK = 64; break;
    }
    int words = rows * WROW_W;
    if (idx < words) {
        int n = idx / WROW_W;
        int kpos = idx - n * WROW_W;
        float f0 = 0.0f, f1 = 0.0f;
        if (kpos < halfK) {
            int k = kpos * 2;
            f0 = wfetch(mode, n, k, Wa, Wb);
            f1 = wfetch(mode, n, k + 1, Wa, Wb);
        }
        dst[idx] = pack_bf2(f0, f1);
    } else if (bb && (idx - words) < 128) {
        g_biasg[slot * 128 + (idx - words)] = __ldg(bb + (idx - words));
    }
}

// ============================ main kernel pieces ============================
__device__ __forceinline__ void stage_copy(void* dst, const uint32_t* src, int words4,
                                           const float* bsrc, float* sbias, int t, int nthr) {
    uint4* d = (uint4*)dst;
    const uint4* s = (const uint4*)src;
    #pragma unroll 4
    for (int i = t; i < words4; i += nthr) d[i] = __ldg(s + i);
    if (bsrc) for (int i = t; i < 128; i += nthr) sbias[i] = __ldg(bsrc + i);
}

// one dense layer: accumulate C[16 m x 128 n] across NCH k-chunks
template<int NCH, int ENCCH>
__device__ __forceinline__ void do_layer(float (&c)[16][4],
    const uint32_t (&Aenc)[16], const uint32_t (&Aact)[32],
    uint32_t wbase, const float* sbias, int lane)
{
    const int nb = (lane & 3) * 2;
    #pragma unroll
    for (int nt = 0; nt < 16; ++nt) {
        float b0v = sbias[nt * 8 + nb];
        float b1v = sbias[nt * 8 + nb + 1];
        c[nt][0] = b0v; c[nt][1] = b1v; c[nt][2] = b0v; c[nt][3] = b1v;
    }
    const uint32_t baddr = wbase + (uint32_t)(lane & 7) * WROW_B + (uint32_t)(lane >> 3) * 16u;
    #pragma unroll
    for (int nt = 0; nt < 16; ++nt) {
        uint32_t bnt = baddr + (uint32_t)nt * (8u * WROW_B);
        #pragma unroll
        for (int kc = 0; kc < NCH; kc += 2) {
            uint32_t b0, b1, b2, b3;
            ldmx4(b0, b1, b2, b3, bnt + (uint32_t)kc * 32u);
            const uint32_t* A0 = (kc < ENCCH) ? &Aenc[kc * 4] : &Aact[(kc - ENCCH) * 4];
            mma_bf16(c[nt], A0[0], A0[1], A0[2], A0[3], b0, b1);
            const uint32_t* A1 = (kc + 1 < ENCCH) ? &Aenc[(kc + 1) * 4] : &Aact[(kc + 1 - ENCCH) * 4];
            mma_bf16(c[nt], A1[0], A1[1], A1[2], A1[3], b2, b3);
        }
    }
}

// relu + cvt bf16 + repack C fragments into next layer's A fragments (pure reg permute)
__device__ __forceinline__ void repack(const float (&c)[16][4], uint32_t (&A)[32]) {
    #pragma unroll
    for (int j = 0; j < 8; ++j) {
        A[j*4+0] = pack_bf2(fmaxf(c[2*j][0], 0.f),   fmaxf(c[2*j][1], 0.f));
        A[j*4+1] = pack_bf2(fmaxf(c[2*j][2], 0.f),   fmaxf(c[2*j][3], 0.f));
        A[j*4+2] = pack_bf2(fmaxf(c[2*j+1][0], 0.f), fmaxf(c[2*j+1][1], 0.f));
        A[j*4+3] = pack_bf2(fmaxf(c[2*j+1][2], 0.f), fmaxf(c[2*j+1][3], 0.f));
    }
}

extern "C" __global__ void __launch_bounds__(NTHREADS, 1)
se3_warp_mma_kernel(
    const float* __restrict__ positions,
    const float* __restrict__ directions,
    const float* __restrict__ warp_code,
    const float* __restrict__ br,
    const float* __restrict__ bv,
    float* __restrict__ out, int N)
{
    extern __shared__ char smc[];
    const uint32_t sb = smem_to_u32(smc);
    const int tid = threadIdx.x;
    const int lane = tid & 31;
    const int warp = tid >> 5;
    const int warpbase = warp * 16;
    const int base = blockIdx.x * TILE_M;

    float* sbias0 = (float*)(smc + SBIAS0_OFF);
    float* sbias1 = (float*)(smc + SBIAS1_OFF);
    float* scr    = (float*)(smc + SCREW_OFF);

    // ---- pre-phase: enc (threads 0..127) || stage L0 weights (threads 128..255) ----
    if (tid < 128) {
        int g = base + tid; if (g >= N) g = N - 1;
        const float TWO_PI = 6.283185307179586f;
        float p0 = positions[g*3+0], p1 = positions[g*3+1], p2 = positions[g*3+2];
        float pp[3] = {p0, p1, p2};
        float vals[64];
        #pragma unroll
        for (int i = 0; i < 3; ++i) {
            float s = TWO_PI * pp[i];
            #pragma unroll
            for (int j = 0; j < 7; ++j) {
                vals[i*7 + j]      = __sinf(s);
                vals[21 + i*7 + j] = __cosf(s);
                s *= 2.0f;
            }
        }
        vals[42] = p0; vals[43] = p1; vals[44] = p2;
        #pragma unroll
        for (int q = 0; q < 8; ++q) vals[45 + q] = warp_code[g*8 + q];
        #pragma unroll
        for (int q = 53; q < 64; ++q) vals[q] = 0.0f;

        char* erow = smc + ENC_OFF + tid * ENC_ROW_B;
        #pragma unroll
        for (int j = 0; j < 32; ++j)
            *(uint32_t*)(erow + j * 4) = pack_bf2(vals[2*j], vals[2*j + 1]);
    } else {
        stage_copy(smc + WB0_OFF, g_wscratch + 0 * SLOT_WORDS, SLOT_WORDS / 4,
                   g_biasg + 0 * 128, sbias0, tid - 128, 128);
    }
    __syncthreads();

    // ---- load enc A fragments (4 k-chunks, kept live for layer 0 and layer 4) ----
    uint32_t Aenc[16];
    {
        const int tileid = lane >> 3;
        const uint32_t arow = (uint32_t)(warpbase + (lane & 7) + (tileid & 1) * 8);
        const uint32_t acol = (uint32_t)((tileid >> 1) * 16);
        uint32_t abase = sb + ENC_OFF + arow * ENC_ROW_B + acol;
        #pragma unroll
        for (int ch = 0; ch < 4; ++ch)
            ldmx4(Aenc[ch*4+0], Aenc[ch*4+1], Aenc[ch*4+2], Aenc[ch*4+3], abase + (uint32_t)ch * 32u);
    }

    float c[16][4];
    uint32_t Aact[32];

    // phase 0: stage L1 -> WB1 ; compute L0 (WB0)
    stage_copy(smc + WB1_OFF, g_wscratch + 1 * SLOT_WORDS, SLOT_WORDS / 4, g_biasg + 128, sbias1, tid, NTHREADS);
    do_layer<4, 4>(c, Aenc, Aact, sb + WB0_OFF, sbias0, lane);
    repack(c, Aact);
    __syncthreads();

    // phase 1: stage L2 -> WB0 ; compute L1 (WB1)
    stage_copy(smc + WB0_OFF, g_wscratch + 2 * SLOT_WORDS, SLOT_WORDS / 4, g_biasg + 256, sbias0, tid, NTHREADS);
    do_layer<8, 0>(c, Aenc, Aact, sb + WB1_OFF, sbias1, lane);
    repack(c, Aact);
    __syncthreads();

    // phase 2: stage L3 -> WB1 ; compute L2 (WB0)
    stage_copy(smc + WB1_OFF, g_wscratch + 3 * SLOT_WORDS, SLOT_WORDS / 4, g_biasg + 384, sbias1, tid, NTHREADS);
    do_layer<8, 0>(c, Aenc, Aact, sb + WB0_OFF, sbias0, lane);
    repack(c, Aact);
    __syncthreads();

    // phase 3: stage L4 -> WB0 ; compute L3 (WB1)
    stage_copy(smc + WB0_OFF, g_wscratch + 4 * SLOT_WORDS, SLOT_WORDS / 4, g_biasg + 512, sbias0, tid, NTHREADS);
    do_layer<8, 0>(c, Aenc, Aact, sb + WB1_OFF, sbias1, lane);
    repack(c, Aact);
    __syncthreads();

    // phase 4: stage L5 -> WB1 ; compute L4 (WB0, K=192 = 4 enc + 8 act chunks)
    stage_copy(smc + WB1_OFF, g_wscratch + 5 * SLOT_WORDS, SLOT_WORDS / 4, g_biasg + 640, sbias1, tid, NTHREADS);
    do_layer<12, 4>(c, Aenc, Aact, sb + WB0_OFF, sbias0, lane);
    repack(c, Aact);
    __syncthreads();

    // phase 5: stage head -> WB0 ; compute L5 (WB1)
    stage_copy(smc + WB0_OFF, g_wscratch + 6 * SLOT_WORDS, (8 * WROW_W) / 4, nullptr, nullptr, tid, NTHREADS);
    do_layer<8, 0>(c, Aenc, Aact, sb + WB1_OFF, sbias1, lane);
    repack(c, Aact);
    __syncthreads();

    // ---- head MMA: screw_pre[16m x 8n] per warp ----
    {
        float hc[4] = {0.f, 0.f, 0.f, 0.f};
        const uint32_t baddr = sb + WB0_OFF + (uint32_t)(lane & 7) * WROW_B + (uint32_t)(lane >> 3) * 16u;
        #pragma unroll
        for (int kc = 0; kc < 8; kc += 2) {
            uint32_t b0, b1, b2, b3;
            ldmx4(b0, b1, b2, b3, baddr + (uint32_t)kc * 32u);
            mma_bf16(hc, Aact[kc*4+0], Aact[kc*4+1], Aact[kc*4+2], Aact[kc*4+3], b0, b1);
            mma_bf16(hc, Aact[(kc+1)*4+0], Aact[(kc+1)*4+1], Aact[(kc+1)*4+2], Aact[(kc+1)*4+3], b2, b3);
        }
        int m0 = warpbase + (lane >> 2);
        int n0 = (lane & 3) * 2;
        scr[m0 * 8 + n0]       = hc[0];
        scr[m0 * 8 + n0 + 1]   = hc[1];
        scr[(m0+8) * 8 + n0]     = hc[2];
        scr[(m0+8) * 8 + n0 + 1] = hc[3];
    }
    __syncthreads();

    // ---- SE(3) exp-map epilogue: one thread per point ----
    if (tid < TILE_M) {
        const int p = tid;
        const int g = base + p;
        if (g < N) {
            float vx = scr[p*8+0] + __ldg(bv + 0);
            float vy = scr[p*8+1] + __ldg(bv + 1);
            float vz = scr[p*8+2] + __ldg(bv + 2);
            float wx = scr[p*8+3] + __ldg(br + 0);
            float wy = scr[p*8+4] + __ldg(br + 1);
            float wz = scr[p*8+5] + __ldg(br + 2);

            float ang2 = fmaxf(wx*wx + wy*wy + wz*wz, 1e-4f);
            float ang  = sqrtf(ang2);
            float sa = sinf(ang), ca = cosf(ang);
            float f1 = sa / ang;
            float f2 = (1.0f - ca) / ang2;
            float f3 = (ang - sa) / (ang * ang2);

            float K[3][3] = {{0.f,  wz, -wy},
                             {-wz, 0.f,  wx},
                             { wy, -wx, 0.f}};
            float KK[3][3];
            #pragma unroll
            for (int a = 0; a < 3; ++a)
                #pragma unroll
                for (int b = 0; b < 3; ++b)
                    KK[a][b] = K[a][0]*K[0][b] + K[a][1]*K[1][b] + K[a][2]*K[2][b];

            float R[3][3], V[3][3];
            #pragma unroll
            for (int a = 0; a < 3; ++a)
                #pragma unroll
                for (int b = 0; b < 3; ++b) {
                    float I = (a == b) ? 1.0f : 0.0f;
                    R[a][b] = I + f1*K[a][b] + f2*KK[a][b];
                    V[a][b] = I + f2*K[a][b] + f3*KK[a][b];
                }
            float T0 = V[0][0]*vx + V[0][1]*vy + V[0][2]*vz;
            float T1 = V[1][0]*vx + V[1][1]*vy + V[1][2]*vz;
            float T2 = V[2][0]*vx + V[2][1]*vy + V[2][2]*vz;

            float px = positions[g*3+0],  py = positions[g*3+1],  pz = positions[g*3+2];
            float dx = directions[g*3+0], dy = directions[g*3+1], dz = directions[g*3+2];

            // M[:3,:3] = R^T, M[:3,3] = T  =>  wp = R^T p + T, wd = R^T d
            float wp0 = R[0][0]*px + R[1][0]*py + R[2][0]*pz + T0;
            float wp1 = R[0][1]*px + R[1][1]*py + R[2][1]*pz + T1;
            float wp2 = R[0][2]*px + R[1][2]*py + R[2][2]*pz + T2;
            float wd0 = R[0][0]*dx + R[1][0]*dy + R[2][0]*dz;
            float wd1 = R[0][1]*dx + R[1][1]*dy + R[2][1]*dz;
            float wd2 = R[0][2]*dx + R[1][2]*dy + R[2][2]*dz;

            wp0 = isnan(wp0) ? px : wp0;
            wp1 = isnan(wp1) ? py : wp1;
            wp2 = isnan(wp2) ? pz : wp2;
            wd0 = isnan(wd0) ? dx : wd0;
            wd1 = isnan(wd1) ? dy : wd1;
            wd2 = isnan(wd2) ? dz : wd2;

            out[g*3+0] = wp0; out[g*3+1] = wp1; out[g*3+2] = wp2;
            long long off = 3LL * N;
            out[off + g*3+0] = wd0; out[off + g*3+1] = wd1; out[off + g*3+2] = wd2;
        }
    }
}

// ============================ launch ============================
extern "C" void kernel_launch(void* const* d_in, const int* in_sizes, int n_in,
                              void* d_out, int out_size) {
    const float* positions  = (const float*)d_in[0];
    const float* directions = (const float*)d_in[1];
    const float* warp_code  = (const float*)d_in[2];
    const float* W0 = (const float*)d_in[3];  const float* b0 = (const float*)d_in[4];
    const float* W1 = (const float*)d_in[5];  const float* b1 = (const float*)d_in[6];
    const float* W2 = (const float*)d_in[7];  const float* b2 = (const float*)d_in[8];
    const float* W3 = (const float*)d_in[9];  const float* b3 = (const float*)d_in[10];
    const float* W4 = (const float*)d_in[11]; const float* b4 = (const float*)d_in[12];
    const float* W5 = (const float*)d_in[13]; const float* b5 = (const float*)d_in[14];
    const float* Wr = (const float*)d_in[15]; const float* br = (const float*)d_in[16];
    const float* Wv = (const float*)d_in[17]; const float* bv = (const float*)d_in[18];

    int N = in_sizes[0] / 3;
    int blocks = (N + TILE_M - 1) / TILE_M;

    dim3 pgrid(51, 7);
    prep_weights<<<pgrid, 256>>>(W0, W1, W2, W3, W4, W5, Wv, Wr,
                                 b0, b1, b2, b3, b4, b5);

    cudaFuncSetAttribute(se3_warp_mma_kernel,
                         cudaFuncAttributeMaxDynamicSharedMemorySize, SMEM_BYTES);
    se3_warp_mma_kernel<<<blocks, NTHREADS, SMEM_BYTES>>>(
        positions, directions, warp_code, br, bv, (float*)d_out, N);
}

// round 8
// speedup vs baseline: 24.9891x; 1.4324x over previous
#include <cuda_runtime.h>
#include <cuda_fp16.h>
#include <cstdint>
#include <math.h>

// ============================ config ============================
#define NTHREADS 256
#define TILE_M   256          // 8 warps x m=32

// weight row stride: 400 B (100 words; 100%32=4 -> conflict-free ldmatrix rows)
#define WROW_B   400
#define WROW_W   100
#define SLOT_WORDS (128 * WROW_W)      // 12800 u32 per weight slot

// smem layout (bytes)
#define ENC_OFF    0                   // 256 rows x 144 B
#define ENC_ROW_B  144
#define WB0_OFF    36864               // 128 x 400 B
#define WB1_OFF    88064
#define SBIAS0_OFF 139264              // 128 f32
#define SBIAS1_OFF 139776
#define SCREW_OFF  140288              // 256 x 8 f32
#define SMEM_BYTES 148480

__device__ uint32_t g_wscratch[7 * SLOT_WORDS];   // f16x2-packed: L0..L5, head
__device__ float    g_biasg[6 * 128];

// ============================ helpers ============================
__device__ __forceinline__ uint32_t smem_to_u32(const void* p) {
    uint32_t a;
    asm("{ .reg .u64 t; cvta.to.shared.u64 t, %1; cvt.u32.u64 %0, t; }" : "=r"(a) : "l"(p));
    return a;
}

__device__ __forceinline__ void ldmx4(uint32_t& r0, uint32_t& r1, uint32_t& r2, uint32_t& r3, uint32_t addr) {
    asm volatile("ldmatrix.sync.aligned.m8n8.x4.shared.b16 {%0,%1,%2,%3}, [%4];"
        : "=r"(r0), "=r"(r1), "=r"(r2), "=r"(r3) : "r"(addr));
}

// f16 inputs, f16 accumulators (C packed f16x2: c0 = row r, c1 = row r+8)
__device__ __forceinline__ void mma_h(uint32_t (&c)[2],
    uint32_t a0, uint32_t a1, uint32_t a2, uint32_t a3, uint32_t b0, uint32_t b1) {
    asm volatile("mma.sync.aligned.m16n8k16.row.col.f16.f16.f16.f16 "
        "{%0,%1}, {%2,%3,%4,%5}, {%6,%7}, {%0,%1};"
        : "+r"(c[0]), "+r"(c[1])
        : "r"(a0), "r"(a1), "r"(a2), "r"(a3), "r"(b0), "r"(b1));
}

// f16 inputs, f32 accumulators (head)
__device__ __forceinline__ void mma_hf32(float (&c)[4],
    uint32_t a0, uint32_t a1, uint32_t a2, uint32_t a3, uint32_t b0, uint32_t b1) {
    asm volatile("mma.sync.aligned.m16n8k16.row.col.f32.f16.f16.f32 "
        "{%0,%1,%2,%3}, {%4,%5,%6,%7}, {%8,%9}, {%0,%1,%2,%3};"
        : "+f"(c[0]), "+f"(c[1]), "+f"(c[2]), "+f"(c[3])
        : "r"(a0), "r"(a1), "r"(a2), "r"(a3), "r"(b0), "r"(b1));
}

__device__ __forceinline__ uint32_t pack_h2(float lo, float hi) {
    __half2 h = __floats2half2_rn(lo, hi);
    return *reinterpret_cast<uint32_t*>(&h);
}

__device__ __forceinline__ uint32_t relu_h2(uint32_t x) {
    __half2 h = *reinterpret_cast<__half2*>(&x);
    h = __hmax2(h, __float2half2_rn(0.0f));
    return *reinterpret_cast<uint32_t*>(&h);
}

// weight fetch with layer-specific padding/remap
__device__ __forceinline__ float wfetch(int mode, int n, int k, const float* Wa, const float* Wb) {
    if (mode == 0) return __ldg(Wa + n * 128 + k);                   // fan_in 128
    if (mode == 1) return (k < 53) ? __ldg(Wa + n * 53 + k) : 0.0f;  // L0: 53 -> pad 64
    if (mode == 2) {                                                 // L4: concat(53 pad 64, 128)
        if (k < 53) return __ldg(Wa + n * 181 + k);
        if (k < 64) return 0.0f;
        return __ldg(Wa + n * 181 + (k - 11));
    }
    // mode 3: head rows = [Wv0..2, Wr0..2, 0, 0]
    if (n < 3) return __ldg(Wa + n * 128 + k);
    if (n < 6) return __ldg(Wb + (n - 3) * 128 + k);
    return 0.0f;
}

// ============================ prep kernel ============================
__global__ void prep_weights(
    const float* W0, const float* W1, const float* W2, const float* W3,
    const float* W4, const float* W5, const float* Wv, const float* Wr,
    const float* b0, const float* b1, const float* b2, const float* b3,
    const float* b4, const float* b5)
{
    int slot = blockIdx.y;
    int idx = blockIdx.x * 256 + threadIdx.x;
    uint32_t* dst = g_wscratch + slot * SLOT_WORDS;

    const float *Wa = nullptr, *Wb = nullptr, *bb = nullptr;
    int mode = 0, rows = 128, halfK = 64;
    switch (slot) {
        case 0: Wa = W0; mode = 1; halfK = 32; bb = b0; break;
        case 1: Wa = W1; mode = 0; halfK = 64; bb = b1; break;
        case 2: Wa = W2; mode = 0; halfK = 64; bb = b2; break;
        case 3: Wa = W3; mode = 0; halfK = 64; bb = b3; break;
        case 4: Wa = W4; mode = 2; halfK = 96; bb = b4; break;
        case 5: Wa = W5; mode = 0; halfK = 64; bb = b5; break;
        case 6: Wa = Wv; Wb = Wr; mode = 3; rows = 8; halfK = 64; break;
    }
    int words = rows * WROW_W;
    if (idx < words) {
        int n = idx / WROW_W;
        int kpos = idx - n * WROW_W;
        float f0 = 0.0f, f1 = 0.0f;
        if (kpos < halfK) {
            int k = kpos * 2;
            f0 = wfetch(mode, n, k, Wa, Wb);
            f1 = wfetch(mode, n, k + 1, Wa, Wb);
        }
        dst[idx] = pack_h2(f0, f1);
    } else if (bb && (idx - words) < 128) {
        g_biasg[slot * 128 + (idx - words)] = __ldg(bb + (idx - words));
    }
}

// ============================ main kernel pieces ============================
__device__ __forceinline__ void stage_copy(void* dst, const uint32_t* src, int words4,
                                           const float* bsrc, float* sbias, int t, int nthr) {
    uint4* d = (uint4*)dst;
    const uint4* s = (const uint4*)src;
    #pragma unroll 4
    for (int i = t; i < words4; i += nthr) d[i] = __ldg(s + i);
    if (bsrc) for (int i = t; i < 128; i += nthr) sbias[i] = __ldg(bsrc + i);
}

// one dense layer: C[2 m-tiles][16 n-tiles][2] (f16x2 accum) over NCH k-chunks
template<int NCH, int ENCCH>
__device__ __forceinline__ void do_layer(uint32_t (&C)[2][16][2],
    const uint32_t (&Aenc)[2][16], const uint32_t (&Aact)[2][32],
    uint32_t wbase, const float* sbias, int lane)
{
    const int nb = (lane & 3) * 2;
    #pragma unroll
    for (int nt = 0; nt < 16; ++nt) {
        uint32_t bp = pack_h2(sbias[nt * 8 + nb], sbias[nt * 8 + nb + 1]);
        C[0][nt][0] = bp; C[0][nt][1] = bp;
        C[1][nt][0] = bp; C[1][nt][1] = bp;
    }
    const uint32_t baddr = wbase + (uint32_t)(lane & 7) * WROW_B + (uint32_t)(lane >> 3) * 16u;
    #pragma unroll
    for (int nt = 0; nt < 16; ++nt) {
        uint32_t bnt = baddr + (uint32_t)nt * (8u * WROW_B);
        #pragma unroll
        for (int kc = 0; kc < NCH; kc += 2) {
            uint32_t b0, b1, b2, b3;
            ldmx4(b0, b1, b2, b3, bnt + (uint32_t)kc * 32u);
            #pragma unroll
            for (int t = 0; t < 2; ++t) {
                const uint32_t* A0 = (kc < ENCCH) ? &Aenc[t][kc * 4] : &Aact[t][(kc - ENCCH) * 4];
                mma_h(C[t][nt], A0[0], A0[1], A0[2], A0[3], b0, b1);
                const uint32_t* A1 = (kc + 1 < ENCCH) ? &Aenc[t][(kc + 1) * 4] : &Aact[t][(kc + 1 - ENCCH) * 4];
                mma_h(C[t][nt], A1[0], A1[1], A1[2], A1[3], b2, b3);
            }
        }
    }
}

// relu; C f16x2 fragments map 1:1 onto next layer's A fragments
__device__ __forceinline__ void repack(const uint32_t (&C)[2][16][2], uint32_t (&A)[2][32]) {
    #pragma unroll
    for (int t = 0; t < 2; ++t)
        #pragma unroll
        for (int j = 0; j < 8; ++j) {
            A[t][j*4+0] = relu_h2(C[t][2*j][0]);
            A[t][j*4+1] = relu_h2(C[t][2*j][1]);
            A[t][j*4+2] = relu_h2(C[t][2*j+1][0]);
            A[t][j*4+3] = relu_h2(C[t][2*j+1][1]);
        }
}

extern "C" __global__ void __launch_bounds__(NTHREADS, 1)
se3_warp_mma_kernel(
    const float* __restrict__ positions,
    const float* __restrict__ directions,
    const float* __restrict__ warp_code,
    const float* __restrict__ br,
    const float* __restrict__ bv,
    float* __restrict__ out, int N)
{
    extern __shared__ char smc[];
    const uint32_t sb = smem_to_u32(smc);
    const int tid = threadIdx.x;
    const int lane = tid & 31;
    const int warp = tid >> 5;
    const int warpbase = warp * 32;
    const int base = blockIdx.x * TILE_M;

    float* sbias0 = (float*)(smc + SBIAS0_OFF);
    float* sbias1 = (float*)(smc + SBIAS1_OFF);
    float* scr    = (float*)(smc + SCREW_OFF);

    // ---- pre-phase: every thread encodes one point; then all stage L0 ----
    {
        int g = base + tid; if (g >= N) g = N - 1;
        const float TWO_PI = 6.283185307179586f;
        float p0 = positions[g*3+0], p1 = positions[g*3+1], p2 = positions[g*3+2];
        float pp[3] = {p0, p1, p2};
        float vals[64];
        #pragma unroll
        for (int i = 0; i < 3; ++i) {
            float s = TWO_PI * pp[i];
            #pragma unroll
            for (int j = 0; j < 7; ++j) {
                vals[i*7 + j]      = __sinf(s);
                vals[21 + i*7 + j] = __cosf(s);
                s *= 2.0f;
            }
        }
        vals[42] = p0; vals[43] = p1; vals[44] = p2;
        #pragma unroll
        for (int q = 0; q < 8; ++q) vals[45 + q] = warp_code[g*8 + q];
        #pragma unroll
        for (int q = 53; q < 64; ++q) vals[q] = 0.0f;

        char* erow = smc + ENC_OFF + tid * ENC_ROW_B;
        #pragma unroll
        for (int j = 0; j < 32; ++j)
            *(uint32_t*)(erow + j * 4) = pack_h2(vals[2*j], vals[2*j + 1]);
    }
    stage_copy(smc + WB0_OFF, g_wscratch + 0 * SLOT_WORDS, SLOT_WORDS / 4,
               g_biasg + 0 * 128, sbias0, tid, NTHREADS);
    __syncthreads();

    // ---- load enc A fragments (4 k-chunks x 2 m-tiles; live through layer 4) ----
    uint32_t Aenc[2][16];
    {
        const int tileid = lane >> 3;
        const uint32_t arow_off = (uint32_t)((lane & 7) + (tileid & 1) * 8);
        const uint32_t acol = (uint32_t)((tileid >> 1) * 16);
        #pragma unroll
        for (int t = 0; t < 2; ++t) {
            uint32_t abase = sb + ENC_OFF + (uint32_t)(warpbase + t * 16) * ENC_ROW_B
                           + arow_off * ENC_ROW_B + acol;
            #pragma unroll
            for (int ch = 0; ch < 4; ++ch)
                ldmx4(Aenc[t][ch*4+0], Aenc[t][ch*4+1], Aenc[t][ch*4+2], Aenc[t][ch*4+3],
                      abase + (uint32_t)ch * 32u);
        }
    }

    uint32_t C[2][16][2];
    uint32_t Aact[2][32];

    // phase 0: stage L1 -> WB1 ; compute L0 (WB0)
    stage_copy(smc + WB1_OFF, g_wscratch + 1 * SLOT_WORDS, SLOT_WORDS / 4, g_biasg + 128, sbias1, tid, NTHREADS);
    do_layer<4, 4>(C, Aenc, Aact, sb + WB0_OFF, sbias0, lane);
    repack(C, Aact);
    __syncthreads();

    // phase 1: stage L2 -> WB0 ; compute L1 (WB1)
    stage_copy(smc + WB0_OFF, g_wscratch + 2 * SLOT_WORDS, SLOT_WORDS / 4, g_biasg + 256, sbias0, tid, NTHREADS);
    do_layer<8, 0>(C, Aenc, Aact, sb + WB1_OFF, sbias1, lane);
    repack(C, Aact);
    __syncthreads();

    // phase 2: stage L3 -> WB1 ; compute L2 (WB0)
    stage_copy(smc + WB1_OFF, g_wscratch + 3 * SLOT_WORDS, SLOT_WORDS / 4, g_biasg + 384, sbias1, tid, NTHREADS);
    do_layer<8, 0>(C, Aenc, Aact, sb + WB0_OFF, sbias0, lane);
    repack(C, Aact);
    __syncthreads();

    // phase 3: stage L4 -> WB0 ; compute L3 (WB1)
    stage_copy(smc + WB0_OFF, g_wscratch + 4 * SLOT_WORDS, SLOT_WORDS / 4, g_biasg + 512, sbias0, tid, NTHREADS);
    do_layer<8, 0>(C, Aenc, Aact, sb + WB1_OFF, sbias1, lane);
    repack(C, Aact);
    __syncthreads();

    // phase 4: stage L5 -> WB1 ; compute L4 (WB0, K = 4 enc + 8 act chunks)
    stage_copy(smc + WB1_OFF, g_wscratch + 5 * SLOT_WORDS, SLOT_WORDS / 4, g_biasg + 640, sbias1, tid, NTHREADS);
    do_layer<12, 4>(C, Aenc, Aact, sb + WB0_OFF, sbias0, lane);
    repack(C, Aact);
    __syncthreads();

    // phase 5: stage head -> WB0 ; compute L5 (WB1)
    stage_copy(smc + WB0_OFF, g_wscratch + 6 * SLOT_WORDS, (8 * WROW_W) / 4, nullptr, nullptr, tid, NTHREADS);
    do_layer<8, 0>(C, Aenc, Aact, sb + WB1_OFF, sbias1, lane);
    repack(C, Aact);
    __syncthreads();

    // ---- head MMA (f32 accum): screw_pre[32m x 8n] per warp ----
    {
        float hc[2][4] = {{0.f,0.f,0.f,0.f},{0.f,0.f,0.f,0.f}};
        const uint32_t baddr = sb + WB0_OFF + (uint32_t)(lane & 7) * WROW_B + (uint32_t)(lane >> 3) * 16u;
        #pragma unroll
        for (int kc = 0; kc < 8; kc += 2) {
            uint32_t b0, b1, b2, b3;
            ldmx4(b0, b1, b2, b3, baddr + (uint32_t)kc * 32u);
            #pragma unroll
            for (int t = 0; t < 2; ++t) {
                mma_hf32(hc[t], Aact[t][kc*4+0], Aact[t][kc*4+1], Aact[t][kc*4+2], Aact[t][kc*4+3], b0, b1);
                mma_hf32(hc[t], Aact[t][(kc+1)*4+0], Aact[t][(kc+1)*4+1], Aact[t][(kc+1)*4+2], Aact[t][(kc+1)*4+3], b2, b3);
            }
        }
        int n0 = (lane & 3) * 2;
        #pragma unroll
        for (int t = 0; t < 2; ++t) {
            int m0 = warpbase + t * 16 + (lane >> 2);
            scr[m0 * 8 + n0]         = hc[t][0];
            scr[m0 * 8 + n0 + 1]     = hc[t][1];
            scr[(m0 + 8) * 8 + n0]     = hc[t][2];
            scr[(m0 + 8) * 8 + n0 + 1] = hc[t][3];
        }
    }
    __syncthreads();

    // ---- SE(3) exp-map epilogue: one thread per point ----
    {
        const int p = tid;
        const int g = base + p;
        if (g < N) {
            float vx = scr[p*8+0] + __ldg(bv + 0);
            float vy = scr[p*8+1] + __ldg(bv + 1);
            float vz = scr[p*8+2] + __ldg(bv + 2);
            float wx = scr[p*8+3] + __ldg(br + 0);
            float wy = scr[p*8+4] + __ldg(br + 1);
            float wz = scr[p*8+5] + __ldg(br + 2);

            float ang2 = fmaxf(wx*wx + wy*wy + wz*wz, 1e-4f);
            float ang  = sqrtf(ang2);
            float sa = sinf(ang), ca = cosf(ang);
            float f1 = sa / ang;
            float f2 = (1.0f - ca) / ang2;
            float f3 = (ang - sa) / (ang * ang2);

            float K[3][3] = {{0.f,  wz, -wy},
                             {-wz, 0.f,  wx},
                             { wy, -wx, 0.f}};
            float KK[3][3];
            #pragma unroll
            for (int a = 0; a < 3; ++a)
                #pragma unroll
                for (int b = 0; b < 3; ++b)
                    KK[a][b] = K[a][0]*K[0][b] + K[a][1]*K[1][b] + K[a][2]*K[2][b];

            float R[3][3], V[3][3];
            #pragma unroll
            for (int a = 0; a < 3; ++a)
                #pragma unroll
                for (int b = 0; b < 3; ++b) {
                    float I = (a == b) ? 1.0f : 0.0f;
                    R[a][b] = I + f1*K[a][b] + f2*KK[a][b];
                    V[a][b] = I + f2*K[a][b] + f3*KK[a][b];
                }
            float T0 = V[0][0]*vx + V[0][1]*vy + V[0][2]*vz;
            float T1 = V[1][0]*vx + V[1][1]*vy + V[1][2]*vz;
            float T2 = V[2][0]*vx + V[2][1]*vy + V[2][2]*vz;

            float px = positions[g*3+0],  py = positions[g*3+1],  pz = positions[g*3+2];
            float dx = directions[g*3+0], dy = directions[g*3+1], dz = directions[g*3+2];

            // M[:3,:3] = R^T, M[:3,3] = T  =>  wp = R^T p + T, wd = R^T d
            float wp0 = R[0][0]*px + R[1][0]*py + R[2][0]*pz + T0;
            float wp1 = R[0][1]*px + R[1][1]*py + R[2][1]*pz + T1;
            float wp2 = R[0][2]*px + R[1][2]*py + R[2][2]*pz + T2;
            float wd0 = R[0][0]*dx + R[1][0]*dy + R[2][0]*dz;
            float wd1 = R[0][1]*dx + R[1][1]*dy + R[2][1]*dz;
            float wd2 = R[0][2]*dx + R[1][2]*dy + R[2][2]*dz;

            wp0 = isnan(wp0) ? px : wp0;
            wp1 = isnan(wp1) ? py : wp1;
            wp2 = isnan(wp2) ? pz : wp2;
            wd0 = isnan(wd0) ? dx : wd0;
            wd1 = isnan(wd1) ? dy : wd1;
            wd2 = isnan(wd2) ? dz : wd2;

            out[g*3+0] = wp0; out[g*3+1] = wp1; out[g*3+2] = wp2;
            long long off = 3LL * N;
            out[off + g*3+0] = wd0; out[off + g*3+1] = wd1; out[off + g*3+2] = wd2;
        }
    }
}

// ============================ launch ============================
extern "C" void kernel_launch(void* const* d_in, const int* in_sizes, int n_in,
                              void* d_out, int out_size) {
    const float* positions  = (const float*)d_in[0];
    const float* directions = (const float*)d_in[1];
    const float* warp_code  = (const float*)d_in[2];
    const float* W0 = (const float*)d_in[3];  const float* b0 = (const float*)d_in[4];
    const float* W1 = (const float*)d_in[5];  const float* b1 = (const float*)d_in[6];
    const float* W2 = (const float*)d_in[7];  const float* b2 = (const float*)d_in[8];
    const float* W3 = (const float*)d_in[9];  const float* b3 = (const float*)d_in[10];
    const float* W4 = (const float*)d_in[11]; const float* b4 = (const float*)d_in[12];
    const float* W5 = (const float*)d_in[13]; const float* b5 = (const float*)d_in[14];
    const float* Wr = (const float*)d_in[15]; const float* br = (const float*)d_in[16];
    const float* Wv = (const float*)d_in[17]; const float* bv = (const float*)d_in[18];

    int N = in_sizes[0] / 3;
    int blocks = (N + TILE_M - 1) / TILE_M;

    dim3 pgrid(51, 7);
    prep_weights<<<pgrid, 256>>>(W0, W1, W2, W3, W4, W5, Wv, Wr,
                                 b0, b1, b2, b3, b4, b5);

    cudaFuncSetAttribute(se3_warp_mma_kernel,
                         cudaFuncAttributeMaxDynamicSharedMemorySize, SMEM_BYTES);
    se3_warp_mma_kernel<<<blocks, NTHREADS, SMEM_BYTES>>>(
        positions, directions, warp_code, br, bv, (float*)d_out, N);
}

// round 9
// speedup vs baseline: 30.1543x; 1.2067x over previous
#include <cuda_runtime.h>
#include <cuda_fp16.h>
#include <cstdint>
#include <math.h>

// ============================ config ============================
#define NTHREADS 256
#define TILE_M   256          // 8 warps x m=32

// weight row stride: 400 B (100 words; 100%32=4 -> conflict-free ldmatrix rows)
#define WROW_B   400
#define WROW_W   100
#define SLOT_WORDS (128 * WROW_W)      // 12800 u32 per weight slot

// smem layout (bytes)
#define ENC_OFF    0                   // 256 rows x 144 B
#define ENC_ROW_B  144
#define WB0_OFF    36864               // 128 x 400 B
#define WB1_OFF    88064
#define SBIAS0_OFF 139264              // 128 f32
#define SBIAS1_OFF 139776
#define SCREW_OFF  140288              // 256 x 8 f32
#define SMEM_BYTES 148480

__device__ uint32_t g_wscratch[7 * SLOT_WORDS];   // f16x2-packed: L0..L5, head
__device__ float    g_biasg[6 * 128];

// ============================ helpers ============================
__device__ __forceinline__ uint32_t smem_to_u32(const void* p) {
    uint32_t a;
    asm("{ .reg .u64 t; cvta.to.shared.u64 t, %1; cvt.u32.u64 %0, t; }" : "=r"(a) : "l"(p));
    return a;
}

__device__ __forceinline__ void ldmx4(uint32_t& r0, uint32_t& r1, uint32_t& r2, uint32_t& r3, uint32_t addr) {
    asm volatile("ldmatrix.sync.aligned.m8n8.x4.shared.b16 {%0,%1,%2,%3}, [%4];"
        : "=r"(r0), "=r"(r1), "=r"(r2), "=r"(r3) : "r"(addr));
}

// f16 inputs, f16 accumulators (C packed f16x2: c0 = row r, c1 = row r+8)
__device__ __forceinline__ void mma_h(uint32_t (&c)[2],
    uint32_t a0, uint32_t a1, uint32_t a2, uint32_t a3, uint32_t b0, uint32_t b1) {
    asm volatile("mma.sync.aligned.m16n8k16.row.col.f16.f16.f16.f16 "
        "{%0,%1}, {%2,%3,%4,%5}, {%6,%7}, {%0,%1};"
        : "+r"(c[0]), "+r"(c[1])
        : "r"(a0), "r"(a1), "r"(a2), "r"(a3), "r"(b0), "r"(b1));
}

// f16 inputs, f32 accumulators (head)
__device__ __forceinline__ void mma_hf32(float (&c)[4],
    uint32_t a0, uint32_t a1, uint32_t a2, uint32_t a3, uint32_t b0, uint32_t b1) {
    asm volatile("mma.sync.aligned.m16n8k16.row.col.f32.f16.f16.f32 "
        "{%0,%1,%2,%3}, {%4,%5,%6,%7}, {%8,%9}, {%0,%1,%2,%3};"
        : "+f"(c[0]), "+f"(c[1]), "+f"(c[2]), "+f"(c[3])
        : "r"(a0), "r"(a1), "r"(a2), "r"(a3), "r"(b0), "r"(b1));
}

__device__ __forceinline__ uint32_t pack_h2(float lo, float hi) {
    __half2 h = __floats2half2_rn(lo, hi);
    return *reinterpret_cast<uint32_t*>(&h);
}

__device__ __forceinline__ uint32_t relu_h2(uint32_t x) {
    __half2 h = *reinterpret_cast<__half2*>(&x);
    h = __hmax2(h, __float2half2_rn(0.0f));
    return *reinterpret_cast<uint32_t*>(&h);
}

// cp.async 16B
__device__ __forceinline__ void cp_async16(uint32_t dst, const void* src) {
    asm volatile("cp.async.cg.shared.global [%0], [%1], 16;" :: "r"(dst), "l"(src));
}
#define CP_COMMIT()   asm volatile("cp.async.commit_group;" ::: "memory")
#define CP_WAIT_ALL() asm volatile("cp.async.wait_all;" ::: "memory")

// weight fetch with layer-specific padding/remap
__device__ __forceinline__ float wfetch(int mode, int n, int k, const float* Wa, const float* Wb) {
    if (mode == 0) return __ldg(Wa + n * 128 + k);                   // fan_in 128
    if (mode == 1) return (k < 53) ? __ldg(Wa + n * 53 + k) : 0.0f;  // L0: 53 -> pad 64
    if (mode == 2) {                                                 // L4: concat(53 pad 64, 128)
        if (k < 53) return __ldg(Wa + n * 181 + k);
        if (k < 64) return 0.0f;
        return __ldg(Wa + n * 181 + (k - 11));
    }
    // mode 3: head rows = [Wv0..2, Wr0..2, 0, 0]
    if (n < 3) return __ldg(Wa + n * 128 + k);
    if (n < 6) return __ldg(Wb + (n - 3) * 128 + k);
    return 0.0f;
}

// ============================ prep kernel ============================
__global__ void prep_weights(
    const float* W0, const float* W1, const float* W2, const float* W3,
    const float* W4, const float* W5, const float* Wv, const float* Wr,
    const float* b0, const float* b1, const float* b2, const float* b3,
    const float* b4, const float* b5)
{
    int slot = blockIdx.y;
    int idx = blockIdx.x * 256 + threadIdx.x;
    uint32_t* dst = g_wscratch + slot * SLOT_WORDS;

    const float *Wa = nullptr, *Wb = nullptr, *bb = nullptr;
    int mode = 0, rows = 128, halfK = 64;
    switch (slot) {
        case 0: Wa = W0; mode = 1; halfK = 32; bb = b0; break;
        case 1: Wa = W1; mode = 0; halfK = 64; bb = b1; break;
        case 2: Wa = W2; mode = 0; halfK = 64; bb = b2; break;
        case 3: Wa = W3; mode = 0; halfK = 64; bb = b3; break;
        case 4: Wa = W4; mode = 2; halfK = 96; bb = b4; break;
        case 5: Wa = W5; mode = 0; halfK = 64; bb = b5; break;
        case 6: Wa = Wv; Wb = Wr; mode = 3; rows = 8; halfK = 64; break;
    }
    int words = rows * WROW_W;
    if (idx < words) {
        int n = idx / WROW_W;
        int kpos = idx - n * WROW_W;
        float f0 = 0.0f, f1 = 0.0f;
        if (kpos < halfK) {
            int k = kpos * 2;
            f0 = wfetch(mode, n, k, Wa, Wb);
            f1 = wfetch(mode, n, k + 1, Wa, Wb);
        }
        dst[idx] = pack_h2(f0, f1);
    } else if (bb && (idx - words) < 128) {
        g_biasg[slot * 128 + (idx - words)] = __ldg(bb + (idx - words));
    }
}

// ============================ main kernel pieces ============================
// async weight staging: smem dst (u32 addr), gmem src; 16B granules
__device__ __forceinline__ void stage_async(uint32_t dst, const uint32_t* src, int words4,
                                            const float* bsrc, uint32_t sbias_dst, int t, int nthr) {
    const uint4* s = (const uint4*)src;
    #pragma unroll 4
    for (int i = t; i < words4; i += nthr)
        cp_async16(dst + (uint32_t)i * 16u, s + i);
    if (bsrc && t < 32)
        cp_async16(sbias_dst + (uint32_t)t * 16u, (const uint4*)bsrc + t);
}

// one dense layer, kc-outer / nt-inner for 64-wide MMA independence
template<int NCH, int ENCCH>
__device__ __forceinline__ void do_layer(uint32_t (&C)[2][16][2],
    const uint32_t (&Aenc)[2][16], const uint32_t (&Aact)[2][32],
    uint32_t wbase, const float* sbias, int lane)
{
    const int nb = (lane & 3) * 2;
    #pragma unroll
    for (int nt = 0; nt < 16; ++nt) {
        uint32_t bp = pack_h2(sbias[nt * 8 + nb], sbias[nt * 8 + nb + 1]);
        C[0][nt][0] = bp; C[0][nt][1] = bp;
        C[1][nt][0] = bp; C[1][nt][1] = bp;
    }
    const uint32_t baddr = wbase + (uint32_t)(lane & 7) * WROW_B + (uint32_t)(lane >> 3) * 16u;
    #pragma unroll
    for (int kc = 0; kc < NCH; kc += 2) {
        const uint32_t* A00 = (kc     < ENCCH) ? &Aenc[0][kc * 4]           : &Aact[0][(kc - ENCCH) * 4];
        const uint32_t* A01 = (kc     < ENCCH) ? &Aenc[1][kc * 4]           : &Aact[1][(kc - ENCCH) * 4];
        const uint32_t* A10 = (kc + 1 < ENCCH) ? &Aenc[0][(kc + 1) * 4]     : &Aact[0][(kc + 1 - ENCCH) * 4];
        const uint32_t* A11 = (kc + 1 < ENCCH) ? &Aenc[1][(kc + 1) * 4]     : &Aact[1][(kc + 1 - ENCCH) * 4];
        const uint32_t kaddr = baddr + (uint32_t)kc * 32u;
        #pragma unroll
        for (int nt = 0; nt < 16; ++nt) {
            uint32_t b0, b1, b2, b3;
            ldmx4(b0, b1, b2, b3, kaddr + (uint32_t)nt * (8u * WROW_B));
            mma_h(C[0][nt], A00[0], A00[1], A00[2], A00[3], b0, b1);
            mma_h(C[1][nt], A01[0], A01[1], A01[2], A01[3], b0, b1);
            mma_h(C[0][nt], A10[0], A10[1], A10[2], A10[3], b2, b3);
            mma_h(C[1][nt], A11[0], A11[1], A11[2], A11[3], b2, b3);
        }
    }
}

// relu; C f16x2 fragments map 1:1 onto next layer's A fragments
__device__ __forceinline__ void repack(const uint32_t (&C)[2][16][2], uint32_t (&A)[2][32]) {
    #pragma unroll
    for (int t = 0; t < 2; ++t)
        #pragma unroll
        for (int j = 0; j < 8; ++j) {
            A[t][j*4+0] = relu_h2(C[t][2*j][0]);
            A[t][j*4+1] = relu_h2(C[t][2*j][1]);
            A[t][j*4+2] = relu_h2(C[t][2*j+1][0]);
            A[t][j*4+3] = relu_h2(C[t][2*j+1][1]);
        }
}

extern "C" __global__ void __launch_bounds__(NTHREADS, 1)
se3_warp_mma_kernel(
    const float* __restrict__ positions,
    const float* __restrict__ directions,
    const float* __restrict__ warp_code,
    const float* __restrict__ br,
    const float* __restrict__ bv,
    float* __restrict__ out, int N)
{
    extern __shared__ char smc[];
    const uint32_t sb = smem_to_u32(smc);
    const int tid = threadIdx.x;
    const int lane = tid & 31;
    const int warp = tid >> 5;
    const int warpbase = warp * 32;
    const int base = blockIdx.x * TILE_M;

    float* sbias0 = (float*)(smc + SBIAS0_OFF);
    float* sbias1 = (float*)(smc + SBIAS1_OFF);
    float* scr    = (float*)(smc + SCREW_OFF);

    // ---- pre-phase: stage L0 async, then encode one point per thread ----
    stage_async(sb + WB0_OFF, g_wscratch + 0 * SLOT_WORDS, SLOT_WORDS / 4,
                g_biasg + 0 * 128, sb + SBIAS0_OFF, tid, NTHREADS);
    CP_COMMIT();
    {
        int g = base + tid; if (g >= N) g = N - 1;
        const float TWO_PI = 6.283185307179586f;
        float p0 = positions[g*3+0], p1 = positions[g*3+1], p2 = positions[g*3+2];
        float pp[3] = {p0, p1, p2};
        float vals[64];
        #pragma unroll
        for (int i = 0; i < 3; ++i) {
            float s = TWO_PI * pp[i];
            #pragma unroll
            for (int j = 0; j < 7; ++j) {
                vals[i*7 + j]      = __sinf(s);
                vals[21 + i*7 + j] = __cosf(s);
                s *= 2.0f;
            }
        }
        vals[42] = p0; vals[43] = p1; vals[44] = p2;
        #pragma unroll
        for (int q = 0; q < 8; ++q) vals[45 + q] = warp_code[g*8 + q];
        #pragma unroll
        for (int q = 53; q < 64; ++q) vals[q] = 0.0f;

        char* erow = smc + ENC_OFF + tid * ENC_ROW_B;
        #pragma unroll
        for (int j = 0; j < 32; ++j)
            *(uint32_t*)(erow + j * 4) = pack_h2(vals[2*j], vals[2*j + 1]);
    }
    CP_WAIT_ALL();
    __syncthreads();

    // ---- load enc A fragments (4 k-chunks x 2 m-tiles; live through layer 4) ----
    uint32_t Aenc[2][16];
    {
        const int tileid = lane >> 3;
        const uint32_t arow_off = (uint32_t)((lane & 7) + (tileid & 1) * 8);
        const uint32_t acol = (uint32_t)((tileid >> 1) * 16);
        #pragma unroll
        for (int t = 0; t < 2; ++t) {
            uint32_t abase = sb + ENC_OFF + (uint32_t)(warpbase + t * 16) * ENC_ROW_B
                           + arow_off * ENC_ROW_B + acol;
            #pragma unroll
            for (int ch = 0; ch < 4; ++ch)
                ldmx4(Aenc[t][ch*4+0], Aenc[t][ch*4+1], Aenc[t][ch*4+2], Aenc[t][ch*4+3],
                      abase + (uint32_t)ch * 32u);
        }
    }

    uint32_t C[2][16][2];
    uint32_t Aact[2][32];

    // phase 0: stage L1 -> WB1 ; compute L0 (WB0)
    stage_async(sb + WB1_OFF, g_wscratch + 1 * SLOT_WORDS, SLOT_WORDS / 4, g_biasg + 128, sb + SBIAS1_OFF, tid, NTHREADS);
    CP_COMMIT();
    do_layer<4, 4>(C, Aenc, Aact, sb + WB0_OFF, sbias0, lane);
    repack(C, Aact);
    CP_WAIT_ALL();
    __syncthreads();

    // phase 1: stage L2 -> WB0 ; compute L1 (WB1)
    stage_async(sb + WB0_OFF, g_wscratch + 2 * SLOT_WORDS, SLOT_WORDS / 4, g_biasg + 256, sb + SBIAS0_OFF, tid, NTHREADS);
    CP_COMMIT();
    do_layer<8, 0>(C, Aenc, Aact, sb + WB1_OFF, sbias1, lane);
    repack(C, Aact);
    CP_WAIT_ALL();
    __syncthreads();

    // phase 2: stage L3 -> WB1 ; compute L2 (WB0)
    stage_async(sb + WB1_OFF, g_wscratch + 3 * SLOT_WORDS, SLOT_WORDS / 4, g_biasg + 384, sb + SBIAS1_OFF, tid, NTHREADS);
    CP_COMMIT();
    do_layer<8, 0>(C, Aenc, Aact, sb + WB0_OFF, sbias0, lane);
    repack(C, Aact);
    CP_WAIT_ALL();
    __syncthreads();

    // phase 3: stage L4 -> WB0 ; compute L3 (WB1)
    stage_async(sb + WB0_OFF, g_wscratch + 4 * SLOT_WORDS, SLOT_WORDS / 4, g_biasg + 512, sb + SBIAS0_OFF, tid, NTHREADS);
    CP_COMMIT();
    do_layer<8, 0>(C, Aenc, Aact, sb + WB1_OFF, sbias1, lane);
    repack(C, Aact);
    CP_WAIT_ALL();
    __syncthreads();

    // phase 4: stage L5 -> WB1 ; compute L4 (WB0, K = 4 enc + 8 act chunks)
    stage_async(sb + WB1_OFF, g_wscratch + 5 * SLOT_WORDS, SLOT_WORDS / 4, g_biasg + 640, sb + SBIAS1_OFF, tid, NTHREADS);
    CP_COMMIT();
    do_layer<12, 4>(C, Aenc, Aact, sb + WB0_OFF, sbias0, lane);
    repack(C, Aact);
    CP_WAIT_ALL();
    __syncthreads();

    // phase 5: stage head -> WB0 ; compute L5 (WB1)
    stage_async(sb + WB0_OFF, g_wscratch + 6 * SLOT_WORDS, (8 * WROW_W) / 4, nullptr, 0, tid, NTHREADS);
    CP_COMMIT();
    do_layer<8, 0>(C, Aenc, Aact, sb + WB1_OFF, sbias1, lane);
    repack(C, Aact);
    CP_WAIT_ALL();
    __syncthreads();

    // ---- head MMA (f32 accum): screw_pre[32m x 8n] per warp ----
    {
        float hc[2][4] = {{0.f,0.f,0.f,0.f},{0.f,0.f,0.f,0.f}};
        const uint32_t baddr = sb + WB0_OFF + (uint32_t)(lane & 7) * WROW_B + (uint32_t)(lane >> 3) * 16u;
        #pragma unroll
        for (int kc = 0; kc < 8; kc += 2) {
            uint32_t b0, b1, b2, b3;
            ldmx4(b0, b1, b2, b3, baddr + (uint32_t)kc * 32u);
            #pragma unroll
            for (int t = 0; t < 2; ++t) {
                mma_hf32(hc[t], Aact[t][kc*4+0], Aact[t][kc*4+1], Aact[t][kc*4+2], Aact[t][kc*4+3], b0, b1);
                mma_hf32(hc[t], Aact[t][(kc+1)*4+0], Aact[t][(kc+1)*4+1], Aact[t][(kc+1)*4+2], Aact[t][(kc+1)*4+3], b2, b3);
            }
        }
        int n0 = (lane & 3) * 2;
        #pragma unroll
        for (int t = 0; t < 2; ++t) {
            int m0 = warpbase + t * 16 + (lane >> 2);
            scr[m0 * 8 + n0]         = hc[t][0];
            scr[m0 * 8 + n0 + 1]     = hc[t][1];
            scr[(m0 + 8) * 8 + n0]     = hc[t][2];
            scr[(m0 + 8) * 8 + n0 + 1] = hc[t][3];
        }
    }
    __syncthreads();

    // ---- SE(3) exp-map epilogue: one thread per point ----
    {
        const int p = tid;
        const int g = base + p;
        if (g < N) {
            float vx = scr[p*8+0] + __ldg(bv + 0);
            float vy = scr[p*8+1] + __ldg(bv + 1);
            float vz = scr[p*8+2] + __ldg(bv + 2);
            float wx = scr[p*8+3] + __ldg(br + 0);
            float wy = scr[p*8+4] + __ldg(br + 1);
            float wz = scr[p*8+5] + __ldg(br + 2);

            float ang2 = fmaxf(wx*wx + wy*wy + wz*wz, 1e-4f);
            float ang  = sqrtf(ang2);
            float sa = sinf(ang), ca = cosf(ang);
            float f1 = sa / ang;
            float f2 = (1.0f - ca) / ang2;
            float f3 = (ang - sa) / (ang * ang2);

            float K[3][3] = {{0.f,  wz, -wy},
                             {-wz, 0.f,  wx},
                             { wy, -wx, 0.f}};
            float KK[3][3];
            #pragma unroll
            for (int a = 0; a < 3; ++a)
                #pragma unroll
                for (int b = 0; b < 3; ++b)
                    KK[a][b] = K[a][0]*K[0][b] + K[a][1]*K[1][b] + K[a][2]*K[2][b];

            float R[3][3], V[3][3];
            #pragma unroll
            for (int a = 0; a < 3; ++a)
                #pragma unroll
                for (int b = 0; b < 3; ++b) {
                    float I = (a == b) ? 1.0f : 0.0f;
                    R[a][b] = I + f1*K[a][b] + f2*KK[a][b];
                    V[a][b] = I + f2*K[a][b] + f3*KK[a][b];
                }
            float T0 = V[0][0]*vx + V[0][1]*vy + V[0][2]*vz;
            float T1 = V[1][0]*vx + V[1][1]*vy + V[1][2]*vz;
            float T2 = V[2][0]*vx + V[2][1]*vy + V[2][2]*vz;

            float px = positions[g*3+0],  py = positions[g*3+1],  pz = positions[g*3+2];
            float dx = directions[g*3+0], dy = directions[g*3+1], dz = directions[g*3+2];

            // M[:3,:3] = R^T, M[:3,3] = T  =>  wp = R^T p + T, wd = R^T d
            float wp0 = R[0][0]*px + R[1][0]*py + R[2][0]*pz + T0;
            float wp1 = R[0][1]*px + R[1][1]*py + R[2][1]*pz + T1;
            float wp2 = R[0][2]*px + R[1][2]*py + R[2][2]*pz + T2;
            float wd0 = R[0][0]*dx + R[1][0]*dy + R[2][0]*dz;
            float wd1 = R[0][1]*dx + R[1][1]*dy + R[2][1]*dz;
            float wd2 = R[0][2]*dx + R[1][2]*dy + R[2][2]*dz;

            wp0 = isnan(wp0) ? px : wp0;
            wp1 = isnan(wp1) ? py : wp1;
            wp2 = isnan(wp2) ? pz : wp2;
            wd0 = isnan(wd0) ? dx : wd0;
            wd1 = isnan(wd1) ? dy : wd1;
            wd2 = isnan(wd2) ? dz : wd2;

            out[g*3+0] = wp0; out[g*3+1] = wp1; out[g*3+2] = wp2;
            long long off = 3LL * N;
            out[off + g*3+0] = wd0; out[off + g*3+1] = wd1; out[off + g*3+2] = wd2;
        }
    }
}

// ============================ launch ============================
extern "C" void kernel_launch(void* const* d_in, const int* in_sizes, int n_in,
                              void* d_out, int out_size) {
    const float* positions  = (const float*)d_in[0];
    const float* directions = (const float*)d_in[1];
    const float* warp_code  = (const float*)d_in[2];
    const float* W0 = (const float*)d_in[3];  const float* b0 = (const float*)d_in[4];
    const float* W1 = (const float*)d_in[5];  const float* b1 = (const float*)d_in[6];
    const float* W2 = (const float*)d_in[7];  const float* b2 = (const float*)d_in[8];
    const float* W3 = (const float*)d_in[9];  const float* b3 = (const float*)d_in[10];
    const float* W4 = (const float*)d_in[11]; const float* b4 = (const float*)d_in[12];
    const float* W5 = (const float*)d_in[13]; const float* b5 = (const float*)d_in[14];
    const float* Wr = (const float*)d_in[15]; const float* br = (const float*)d_in[16];
    const float* Wv = (const float*)d_in[17]; const float* bv = (const float*)d_in[18];

    int N = in_sizes[0] / 3;
    int blocks = (N + TILE_M - 1) / TILE_M;

    dim3 pgrid(51, 7);
    prep_weights<<<pgrid, 256>>>(W0, W1, W2, W3, W4, W5, Wv, Wr,
                                 b0, b1, b2, b3, b4, b5);

    cudaFuncSetAttribute(se3_warp_mma_kernel,
                         cudaFuncAttributeMaxDynamicSharedMemorySize, SMEM_BYTES);
    se3_warp_mma_kernel<<<blocks, NTHREADS, SMEM_BYTES>>>(
        positions, directions, warp_code, br, bv, (float*)d_out, N);
}

// round 10
// speedup vs baseline: 33.1630x; 1.0998x over previous
#include <cuda_runtime.h>
#include <cuda_fp16.h>
#include <cstdint>
#include <math.h>

// ============================ config ============================
#define NTHREADS 128
#define TILE_M   128          // 4 warps x m=32, 2 CTAs/SM

// per-slot row strides in u32 words (all ==4 mod 32 -> conflict-free ldmatrix)
// L0: 36 w (144 B, K=64), K=128 layers: 68 w (272 B), L4: 100 w (400 B)
#define WROW0_B  144
#define WROW1_B  272
#define WROW4_B  400

// g_wscratch word offsets per slot {L0,L1,L2,L3,L4,L5,head}
__device__ __constant__ int SLOT_OFF[7] = {0, 4608, 13312, 22016, 30720, 43520, 52224};
__device__ uint32_t g_wscratch[52768];
__device__ float    g_biasg[6 * 128];

// smem layout (bytes)
#define ENC_OFF    0                   // 128 rows x 144 B
#define ENC_ROW_B  144
#define WB0_OFF    18432               // 128 x 400 B (holds L0,L2,L4,head)
#define WB1_OFF    69632               // 128 x 272 B (holds L1,L3,L5)
#define SBIAS0_OFF 104448              // 128 f32
#define SBIAS1_OFF 104960
#define SCREW_OFF  105472              // 128 x 8 f32
#define SMEM_BYTES 109568

// ============================ helpers ============================
__device__ __forceinline__ uint32_t smem_to_u32(const void* p) {
    uint32_t a;
    asm("{ .reg .u64 t; cvta.to.shared.u64 t, %1; cvt.u32.u64 %0, t; }" : "=r"(a) : "l"(p));
    return a;
}

__device__ __forceinline__ void ldmx4(uint32_t& r0, uint32_t& r1, uint32_t& r2, uint32_t& r3, uint32_t addr) {
    asm volatile("ldmatrix.sync.aligned.m8n8.x4.shared.b16 {%0,%1,%2,%3}, [%4];"
        : "=r"(r0), "=r"(r1), "=r"(r2), "=r"(r3) : "r"(addr));
}

// f16 inputs, f16 accumulators
__device__ __forceinline__ void mma_h(uint32_t (&c)[2],
    uint32_t a0, uint32_t a1, uint32_t a2, uint32_t a3, uint32_t b0, uint32_t b1) {
    asm volatile("mma.sync.aligned.m16n8k16.row.col.f16.f16.f16.f16 "
        "{%0,%1}, {%2,%3,%4,%5}, {%6,%7}, {%0,%1};"
        : "+r"(c[0]), "+r"(c[1])
        : "r"(a0), "r"(a1), "r"(a2), "r"(a3), "r"(b0), "r"(b1));
}

// f16 inputs, f32 accumulators (head)
__device__ __forceinline__ void mma_hf32(float (&c)[4],
    uint32_t a0, uint32_t a1, uint32_t a2, uint32_t a3, uint32_t b0, uint32_t b1) {
    asm volatile("mma.sync.aligned.m16n8k16.row.col.f32.f16.f16.f32 "
        "{%0,%1,%2,%3}, {%4,%5,%6,%7}, {%8,%9}, {%0,%1,%2,%3};"
        : "+f"(c[0]), "+f"(c[1]), "+f"(c[2]), "+f"(c[3])
        : "r"(a0), "r"(a1), "r"(a2), "r"(a3), "r"(b0), "r"(b1));
}

__device__ __forceinline__ uint32_t pack_h2(float lo, float hi) {
    __half2 h = __floats2half2_rn(lo, hi);
    return *reinterpret_cast<uint32_t*>(&h);
}

__device__ __forceinline__ uint32_t relu_h2(uint32_t x) {
    __half2 h = *reinterpret_cast<__half2*>(&x);
    h = __hmax2(h, __float2half2_rn(0.0f));
    return *reinterpret_cast<uint32_t*>(&h);
}

__device__ __forceinline__ void cp_async16(uint32_t dst, const void* src) {
    asm volatile("cp.async.cg.shared.global [%0], [%1], 16;" :: "r"(dst), "l"(src));
}
#define CP_COMMIT()   asm volatile("cp.async.commit_group;" ::: "memory")
#define CP_WAIT_ALL() asm volatile("cp.async.wait_all;" ::: "memory")

// weight fetch with layer-specific padding/remap (k = half index)
__device__ __forceinline__ float wfetch(int mode, int n, int k, const float* Wa, const float* Wb) {
    if (mode == 0) return __ldg(Wa + n * 128 + k);                   // fan_in 128
    if (mode == 1) return (k < 53) ? __ldg(Wa + n * 53 + k) : 0.0f;  // L0: 53 -> pad 64
    if (mode == 2) {                                                 // L4: concat(53 pad 64, 128)
        if (k < 53) return __ldg(Wa + n * 181 + k);
        if (k < 64) return 0.0f;
        return __ldg(Wa + n * 181 + (k - 11));
    }
    // mode 3: head rows = [Wv0..2, Wr0..2, 0, 0]
    if (n < 3) return __ldg(Wa + n * 128 + k);
    if (n < 6) return __ldg(Wb + (n - 3) * 128 + k);
    return 0.0f;
}

// ============================ prep kernel ============================
__global__ void prep_weights(
    const float* W0, const float* W1, const float* W2, const float* W3,
    const float* W4, const float* W5, const float* Wv, const float* Wr,
    const float* b0, const float* b1, const float* b2, const float* b3,
    const float* b4, const float* b5)
{
    int slot = blockIdx.y;
    int idx = blockIdx.x * 256 + threadIdx.x;
    uint32_t* dst = g_wscratch + SLOT_OFF[slot];

    const float *Wa = nullptr, *Wb = nullptr, *bb = nullptr;
    int mode = 0, rows = 128, wroww = 68, datw = 64;
    switch (slot) {
        case 0: Wa = W0; mode = 1; wroww = 36;  datw = 32; bb = b0; break;
        case 1: Wa = W1; mode = 0; wroww = 68;  datw = 64; bb = b1; break;
        case 2: Wa = W2; mode = 0; wroww = 68;  datw = 64; bb = b2; break;
        case 3: Wa = W3; mode = 0; wroww = 68;  datw = 64; bb = b3; break;
        case 4: Wa = W4; mode = 2; wroww = 100; datw = 96; bb = b4; break;
        case 5: Wa = W5; mode = 0; wroww = 68;  datw = 64; bb = b5; break;
        case 6: Wa = Wv; Wb = Wr; mode = 3; rows = 8; wroww = 68; datw = 64; break;
    }
    int words = rows * wroww;
    if (idx < words) {
        int n = idx / wroww;
        int kpos = idx - n * wroww;
        float f0 = 0.0f, f1 = 0.0f;
        if (kpos < datw) {
            int k = kpos * 2;
            f0 = wfetch(mode, n, k, Wa, Wb);
            f1 = wfetch(mode, n, k + 1, Wa, Wb);
        }
        dst[idx] = pack_h2(f0, f1);
    } else if (bb && (idx - words) < 128) {
        g_biasg[slot * 128 + (idx - words)] = __ldg(bb + (idx - words));
    }
}

// ============================ main kernel pieces ============================
__device__ __forceinline__ void stage_async(uint32_t dst, const uint32_t* src, int words4,
                                            const float* bsrc, uint32_t sbias_dst, int t, int nthr) {
    const uint4* s = (const uint4*)src;
    #pragma unroll 4
    for (int i = t; i < words4; i += nthr)
        cp_async16(dst + (uint32_t)i * 16u, s + i);
    if (bsrc && t < 32)
        cp_async16(sbias_dst + (uint32_t)t * 16u, (const uint4*)bsrc + t);
}

// one dense layer, kc-outer / nt-inner; WROWB = weight row stride in bytes
template<int NCH, int ENCCH, int WROWB>
__device__ __forceinline__ void do_layer(uint32_t (&C)[2][16][2],
    const uint32_t (&Aenc)[2][16], const uint32_t (&Aact)[2][32],
    uint32_t wbase, const float* sbias, int lane)
{
    const int nb = (lane & 3) * 2;
    #pragma unroll
    for (int nt = 0; nt < 16; ++nt) {
        uint32_t bp = pack_h2(sbias[nt * 8 + nb], sbias[nt * 8 + nb + 1]);
        C[0][nt][0] = bp; C[0][nt][1] = bp;
        C[1][nt][0] = bp; C[1][nt][1] = bp;
    }
    const uint32_t baddr = wbase + (uint32_t)(lane & 7) * WROWB + (uint32_t)(lane >> 3) * 16u;
    #pragma unroll
    for (int kc = 0; kc < NCH; kc += 2) {
        const uint32_t* A00 = (kc     < ENCCH) ? &Aenc[0][kc * 4]       : &Aact[0][(kc - ENCCH) * 4];
        const uint32_t* A01 = (kc     < ENCCH) ? &Aenc[1][kc * 4]       : &Aact[1][(kc - ENCCH) * 4];
        const uint32_t* A10 = (kc + 1 < ENCCH) ? &Aenc[0][(kc + 1) * 4] : &Aact[0][(kc + 1 - ENCCH) * 4];
        const uint32_t* A11 = (kc + 1 < ENCCH) ? &Aenc[1][(kc + 1) * 4] : &Aact[1][(kc + 1 - ENCCH) * 4];
        const uint32_t kaddr = baddr + (uint32_t)kc * 32u;
        #pragma unroll
        for (int nt = 0; nt < 16; ++nt) {
            uint32_t b0, b1, b2, b3;
            ldmx4(b0, b1, b2, b3, kaddr + (uint32_t)nt * (8u * WROWB));
            mma_h(C[0][nt], A00[0], A00[1], A00[2], A00[3], b0, b1);
            mma_h(C[1][nt], A01[0], A01[1], A01[2], A01[3], b0, b1);
            mma_h(C[0][nt], A10[0], A10[1], A10[2], A10[3], b2, b3);
            mma_h(C[1][nt], A11[0], A11[1], A11[2], A11[3], b2, b3);
        }
    }
}

__device__ __forceinline__ void repack(const uint32_t (&C)[2][16][2], uint32_t (&A)[2][32]) {
    #pragma unroll
    for (int t = 0; t < 2; ++t)
        #pragma unroll
        for (int j = 0; j < 8; ++j) {
            A[t][j*4+0] = relu_h2(C[t][2*j][0]);
            A[t][j*4+1] = relu_h2(C[t][2*j][1]);
            A[t][j*4+2] = relu_h2(C[t][2*j+1][0]);
            A[t][j*4+3] = relu_h2(C[t][2*j+1][1]);
        }
}

extern "C" __global__ void __launch_bounds__(NTHREADS, 2)
se3_warp_mma_kernel(
    const float* __restrict__ positions,
    const float* __restrict__ directions,
    const float* __restrict__ warp_code,
    const float* __restrict__ br,
    const float* __restrict__ bv,
    float* __restrict__ out, int N)
{
    extern __shared__ char smc[];
    const uint32_t sb = smem_to_u32(smc);
    const int tid = threadIdx.x;
    const int lane = tid & 31;
    const int warp = tid >> 5;
    const int warpbase = warp * 32;
    const int base = blockIdx.x * TILE_M;

    float* sbias0 = (float*)(smc + SBIAS0_OFF);
    float* sbias1 = (float*)(smc + SBIAS1_OFF);
    float* scr    = (float*)(smc + SCREW_OFF);

    // ---- pre-phase: stage L0 async, then encode one point per thread ----
    stage_async(sb + WB0_OFF, g_wscratch + SLOT_OFF[0], 128 * 36 / 4,
                g_biasg + 0 * 128, sb + SBIAS0_OFF, tid, NTHREADS);
    CP_COMMIT();
    {
        int g = base + tid; if (g >= N) g = N - 1;
        const float TWO_PI = 6.283185307179586f;
        float p0 = positions[g*3+0], p1 = positions[g*3+1], p2 = positions[g*3+2];
        float pp[3] = {p0, p1, p2};
        float vals[64];
        #pragma unroll
        for (int i = 0; i < 3; ++i) {
            float s = TWO_PI * pp[i];
            #pragma unroll
            for (int j = 0; j < 7; ++j) {
                vals[i*7 + j]      = __sinf(s);
                vals[21 + i*7 + j] = __cosf(s);
                s *= 2.0f;
            }
        }
        vals[42] = p0; vals[43] = p1; vals[44] = p2;
        #pragma unroll
        for (int q = 0; q < 8; ++q) vals[45 + q] = warp_code[g*8 + q];
        #pragma unroll
        for (int q = 53; q < 64; ++q) vals[q] = 0.0f;

        char* erow = smc + ENC_OFF + tid * ENC_ROW_B;
        #pragma unroll
        for (int j = 0; j < 32; ++j)
            *(uint32_t*)(erow + j * 4) = pack_h2(vals[2*j], vals[2*j + 1]);
    }
    CP_WAIT_ALL();
    __syncthreads();

    // ---- load enc A fragments (4 k-chunks x 2 m-tiles; live through layer 4) ----
    uint32_t Aenc[2][16];
    {
        const int tileid = lane >> 3;
        const uint32_t arow_off = (uint32_t)((lane & 7) + (tileid & 1) * 8);
        const uint32_t acol = (uint32_t)((tileid >> 1) * 16);
        #pragma unroll
        for (int t = 0; t < 2; ++t) {
            uint32_t abase = sb + ENC_OFF + (uint32_t)(warpbase + t * 16) * ENC_ROW_B
                           + arow_off * ENC_ROW_B + acol;
            #pragma unroll
            for (int ch = 0; ch < 4; ++ch)
                ldmx4(Aenc[t][ch*4+0], Aenc[t][ch*4+1], Aenc[t][ch*4+2], Aenc[t][ch*4+3],
                      abase + (uint32_t)ch * 32u);
        }
    }

    uint32_t C[2][16][2];
    uint32_t Aact[2][32];

    // phase 0: stage L1 -> WB1 (272B rows) ; compute L0 (WB0, 144B rows)
    stage_async(sb + WB1_OFF, g_wscratch + SLOT_OFF[1], 128 * 68 / 4, g_biasg + 128, sb + SBIAS1_OFF, tid, NTHREADS);
    CP_COMMIT();
    do_layer<4, 4, WROW0_B>(C, Aenc, Aact, sb + WB0_OFF, sbias0, lane);
    repack(C, Aact);
    CP_WAIT_ALL();
    __syncthreads();

    // phase 1: stage L2 -> WB0 (272) ; compute L1 (WB1, 272)
    stage_async(sb + WB0_OFF, g_wscratch + SLOT_OFF[2], 128 * 68 / 4, g_biasg + 256, sb + SBIAS0_OFF, tid, NTHREADS);
    CP_COMMIT();
    do_layer<8, 0, WROW1_B>(C, Aenc, Aact, sb + WB1_OFF, sbias1, lane);
    repack(C, Aact);
    CP_WAIT_ALL();
    __syncthreads();

    // phase 2: stage L3 -> WB1 (272) ; compute L2 (WB0, 272)
    stage_async(sb + WB1_OFF, g_wscratch + SLOT_OFF[3], 128 * 68 / 4, g_biasg + 384, sb + SBIAS1_OFF, tid, NTHREADS);
    CP_COMMIT();
    do_layer<8, 0, WROW1_B>(C, Aenc, Aact, sb + WB0_OFF, sbias0, lane);
    repack(C, Aact);
    CP_WAIT_ALL();
    __syncthreads();

    // phase 3: stage L4 -> WB0 (400) ; compute L3 (WB1, 272)
    stage_async(sb + WB0_OFF, g_wscratch + SLOT_OFF[4], 128 * 100 / 4, g_biasg + 512, sb + SBIAS0_OFF, tid, NTHREADS);
    CP_COMMIT();
    do_layer<8, 0, WROW1_B>(C, Aenc, Aact, sb + WB1_OFF, sbias1, lane);
    repack(C, Aact);
    CP_WAIT_ALL();
    __syncthreads();

    // phase 4: stage L5 -> WB1 (272) ; compute L4 (WB0, 400, K = 4 enc + 8 act chunks)
    stage_async(sb + WB1_OFF, g_wscratch + SLOT_OFF[5], 128 * 68 / 4, g_biasg + 640, sb + SBIAS1_OFF, tid, NTHREADS);
    CP_COMMIT();
    do_layer<12, 4, WROW4_B>(C, Aenc, Aact, sb + WB0_OFF, sbias0, lane);
    repack(C, Aact);
    CP_WAIT_ALL();
    __syncthreads();

    // phase 5: stage head -> WB0 (272, 8 rows) ; compute L5 (WB1, 272)
    stage_async(sb + WB0_OFF, g_wscratch + SLOT_OFF[6], 8 * 68 / 4, nullptr, 0, tid, NTHREADS);
    CP_COMMIT();
    do_layer<8, 0, WROW1_B>(C, Aenc, Aact, sb + WB1_OFF, sbias1, lane);
    repack(C, Aact);
    CP_WAIT_ALL();
    __syncthreads();

    // ---- head MMA (f32 accum): screw_pre[32m x 8n] per warp ----
    {
        float hc[2][4] = {{0.f,0.f,0.f,0.f},{0.f,0.f,0.f,0.f}};
        const uint32_t baddr = sb + WB0_OFF + (uint32_t)(lane & 7) * WROW1_B + (uint32_t)(lane >> 3) * 16u;
        #pragma unroll
        for (int kc = 0; kc < 8; kc += 2) {
            uint32_t b0, b1, b2, b3;
            ldmx4(b0, b1, b2, b3, baddr + (uint32_t)kc * 32u);
            #pragma unroll
            for (int t = 0; t < 2; ++t) {
                mma_hf32(hc[t], Aact[t][kc*4+0], Aact[t][kc*4+1], Aact[t][kc*4+2], Aact[t][kc*4+3], b0, b1);
                mma_hf32(hc[t], Aact[t][(kc+1)*4+0], Aact[t][(kc+1)*4+1], Aact[t][(kc+1)*4+2], Aact[t][(kc+1)*4+3], b2, b3);
            }
        }
        int n0 = (lane & 3) * 2;
        #pragma unroll
        for (int t = 0; t < 2; ++t) {
            int m0 = warpbase + t * 16 + (lane >> 2);
            scr[m0 * 8 + n0]           = hc[t][0];
            scr[m0 * 8 + n0 + 1]       = hc[t][1];
            scr[(m0 + 8) * 8 + n0]     = hc[t][2];
            scr[(m0 + 8) * 8 + n0 + 1] = hc[t][3];
        }
    }
    __syncthreads();

    // ---- SE(3) exp-map epilogue: one thread per point ----
    {
        const int p = tid;
        const int g = base + p;
        if (g < N) {
            float vx = scr[p*8+0] + __ldg(bv + 0);
            float vy = scr[p*8+1] + __ldg(bv + 1);
            float vz = scr[p*8+2] + __ldg(bv + 2);
            float wx = scr[p*8+3] + __ldg(br + 0);
            float wy = scr[p*8+4] + __ldg(br + 1);
            float wz = scr[p*8+5] + __ldg(br + 2);

            float ang2 = fmaxf(wx*wx + wy*wy + wz*wz, 1e-4f);
            float ang  = sqrtf(ang2);
            float sa = sinf(ang), ca = cosf(ang);
            float f1 = sa / ang;
            float f2 = (1.0f - ca) / ang2;
            float f3 = (ang - sa) / (ang * ang2);

            float K[3][3] = {{0.f,  wz, -wy},
                             {-wz, 0.f,  wx},
                             { wy, -wx, 0.f}};
            float KK[3][3];
            #pragma unroll
            for (int a = 0; a < 3; ++a)
                #pragma unroll
                for (int b = 0; b < 3; ++b)
                    KK[a][b] = K[a][0]*K[0][b] + K[a][1]*K[1][b] + K[a][2]*K[2][b];

            float R[3][3], V[3][3];
            #pragma unroll
            for (int a = 0; a < 3; ++a)
                #pragma unroll
                for (int b = 0; b < 3; ++b) {
                    float I = (a == b) ? 1.0f : 0.0f;
                    R[a][b] = I + f1*K[a][b] + f2*KK[a][b];
                    V[a][b] = I + f2*K[a][b] + f3*KK[a][b];
                }
            float T0 = V[0][0]*vx + V[0][1]*vy + V[0][2]*vz;
            float T1 = V[1][0]*vx + V[1][1]*vy + V[1][2]*vz;
            float T2 = V[2][0]*vx + V[2][1]*vy + V[2][2]*vz;

            float px = positions[g*3+0],  py = positions[g*3+1],  pz = positions[g*3+2];
            float dx = directions[g*3+0], dy = directions[g*3+1], dz = directions[g*3+2];

            // M[:3,:3] = R^T, M[:3,3] = T  =>  wp = R^T p + T, wd = R^T d
            float wp0 = R[0][0]*px + R[1][0]*py + R[2][0]*pz + T0;
            float wp1 = R[0][1]*px + R[1][1]*py + R[2][1]*pz + T1;
            float wp2 = R[0][2]*px + R[1][2]*py + R[2][2]*pz + T2;
            float wd0 = R[0][0]*dx + R[1][0]*dy + R[2][0]*dz;
            float wd1 = R[0][1]*dx + R[1][1]*dy + R[2][1]*dz;
            float wd2 = R[0][2]*dx + R[1][2]*dy + R[2][2]*dz;

            wp0 = isnan(wp0) ? px : wp0;
            wp1 = isnan(wp1) ? py : wp1;
            wp2 = isnan(wp2) ? pz : wp2;
            wd0 = isnan(wd0) ? dx : wd0;
            wd1 = isnan(wd1) ? dy : wd1;
            wd2 = isnan(wd2) ? dz : wd2;

            out[g*3+0] = wp0; out[g*3+1] = wp1; out[g*3+2] = wp2;
            long long off = 3LL * N;
            out[off + g*3+0] = wd0; out[off + g*3+1] = wd1; out[off + g*3+2] = wd2;
        }
    }
}

// ============================ launch ============================
extern "C" void kernel_launch(void* const* d_in, const int* in_sizes, int n_in,
                              void* d_out, int out_size) {
    const float* positions  = (const float*)d_in[0];
    const float* directions = (const float*)d_in[1];
    const float* warp_code  = (const float*)d_in[2];
    const float* W0 = (const float*)d_in[3];  const float* b0 = (const float*)d_in[4];
    const float* W1 = (const float*)d_in[5];  const float* b1 = (const float*)d_in[6];
    const float* W2 = (const float*)d_in[7];  const float* b2 = (const float*)d_in[8];
    const float* W3 = (const float*)d_in[9];  const float* b3 = (const float*)d_in[10];
    const float* W4 = (const float*)d_in[11]; const float* b4 = (const float*)d_in[12];
    const float* W5 = (const float*)d_in[13]; const float* b5 = (const float*)d_in[14];
    const float* Wr = (const float*)d_in[15]; const float* br = (const float*)d_in[16];
    const float* Wv = (const float*)d_in[17]; const float* bv = (const float*)d_in[18];

    int N = in_sizes[0] / 3;
    int blocks = (N + TILE_M - 1) / TILE_M;

    dim3 pgrid(50, 7);
    prep_weights<<<pgrid, 256>>>(W0, W1, W2, W3, W4, W5, Wv, Wr,
                                 b0, b1, b2, b3, b4, b5);

    cudaFuncSetAttribute(se3_warp_mma_kernel,
                         cudaFuncAttributeMaxDynamicSharedMemorySize, SMEM_BYTES);
    se3_warp_mma_kernel<<<blocks, NTHREADS, SMEM_BYTES>>>(
        positions, directions, warp_code, br, bv, (float*)d_out, N);
}